// round 6
// baseline (speedup 1.0000x reference)
#include <cuda_runtime.h>
#include <cstdint>

// Problem constants
#define HH   80
#define WW   120
#define TT   12
#define CIN  6
#define FF   32
#define NBATCH 2
#define CA   38      // real fused channels: x(6) + state(32)
#define CA_P 40      // padded channel count
#define CAP  44      // padded pixel stride (16B-aligned, conflict-free LDS.128)
#define FA   64      // gates: z(32), r(32)
#define FB   32      // candidate
#define TY   16
#define TX   20
#define SH   (TY+2)
#define SWID (TX+2)
#define TILESX 6
#define TILESY 5
#define NTHREADS 640
#define PAIRS 160
#define NHALO (SH*SWID)  // 396
#define NBLOCKS 120

#define SIN_ELEMS (NHALO*CAP)      // 17424 floats
#define WA_ELEMS  (9*CA_P*FA)      // 23040 floats
#define WB_ELEMS  (9*CA_P*FB)      // 11520 floats
// total smem = (17424+23040+11520)*4 = 207,936 B  (< 227KB cap -> 1 block/SM, 120 resident)

// ---- scratch (static device memory) ----
__device__ float g_h [2*NBATCH*HH*WW*FF];
__device__ float g_z [2*NBATCH*HH*WW*FF];
__device__ float g_rh[2*NBATCH*HH*WW*FF];
__device__ float g_wA[2*WA_ELEMS];
__device__ float g_wB[2*WB_ELEMS];
__device__ float g_bA[2*FA];
__device__ float g_bB[2*FB];
__device__ unsigned g_barC[32];

// ---- f32x2 helpers ----
__device__ __forceinline__ unsigned long long pack2(float v) {
    unsigned long long r;
    asm("mov.b64 %0, {%1, %1};" : "=l"(r) : "r"(__float_as_uint(v)));
    return r;
}
__device__ __forceinline__ void ffma2(unsigned long long& d, unsigned long long a, unsigned long long b) {
    asm("fma.rn.f32x2 %0, %1, %2, %0;" : "+l"(d) : "l"(a), "l"(b));
}
__device__ __forceinline__ void unpack2(unsigned long long v, float& lo, float& hi) {
    unsigned int a, b;
    asm("mov.b64 {%0, %1}, %2;" : "=r"(a), "=r"(b) : "l"(v));
    lo = __uint_as_float(a); hi = __uint_as_float(b);
}
__device__ __forceinline__ float sigm(float v) {
    return __fdividef(1.0f, 1.0f + __expf(-v));
}
__device__ __forceinline__ float ftanh(float v) {
    float e = __expf(-2.0f * v);
    return __fdividef(1.0f - e, 1.0f + e);
}

// ---- device-wide barrier (all NBLOCKS resident by construction) ----
__device__ __forceinline__ void gridbar(int i) {
    __syncthreads();                       // all block threads done with prior phase
    if (threadIdx.x == 0) {
        __threadfence();                   // release: block's global writes visible
        unsigned arrived = atomicAdd(&g_barC[i], 1u) + 1;
        if (arrived < NBLOCKS) {
            volatile unsigned* p = &g_barC[i];
            while (*p < NBLOCKS) __nanosleep(128);
        }
        __threadfence();                   // acquire + L1 invalidate (CCTL.IVALL)
    }
    __syncthreads();
}

// ---- weight repack: [dir][k][c(0..39)][f], zero-pad c=38,39 ----
__global__ void pack_kernel(const float* __restrict__ WxF, const float* __restrict__ bF,
                            const float* __restrict__ WzrF, const float* __restrict__ WhF,
                            const float* __restrict__ WxB, const float* __restrict__ bB,
                            const float* __restrict__ WzrB, const float* __restrict__ WhB)
{
    const int NWTOT = 2*9*CA_P*96;
    for (int i = blockIdx.x*blockDim.x + threadIdx.x; i < NWTOT + 2*96; i += gridDim.x*blockDim.x) {
        if (i < NWTOT) {
            int dir = i / (9*CA_P*96); int r = i - dir*(9*CA_P*96);
            int k = r / (CA_P*96);     r -= k*(CA_P*96);
            int c = r / 96;            int f = r - c*96;
            const float* Wx  = dir ? WxB  : WxF;
            const float* Wzr = dir ? WzrB : WzrF;
            const float* Wh  = dir ? WhB  : WhF;
            float v;
            if (c >= CA)          v = 0.0f;
            else if (c < CIN)     v = Wx [(k*CIN + c)*96 + f];
            else if (f < 64)      v = Wzr[(k*FF + (c-CIN))*64 + f];
            else                  v = Wh [(k*FF + (c-CIN))*32 + (f-64)];
            if (f < 64) g_wA[((dir*9 + k)*CA_P + c)*FA + f]        = v;
            else        g_wB[((dir*9 + k)*CA_P + c)*FB + (f - 64)] = v;
        } else {
            int j = i - NWTOT;
            int dir = j / 96; int f = j - dir*96;
            const float* bb = dir ? bB : bF;
            if (f < 64) g_bA[dir*FA + f]      = bb[f];
            else        g_bB[dir*FB + f - 64] = bb[f];
        }
    }
}

__global__ void zero_h_kernel() {
    const int n = 2*NBATCH*HH*WW*FF;
    for (int i = blockIdx.x*blockDim.x + threadIdx.x; i < n; i += gridDim.x*blockDim.x)
        g_h[i] = 0.0f;
    if (blockIdx.x == 0 && threadIdx.x < 32) g_barC[threadIdx.x] = 0;
}

// shared tile loader: one halo pixel per thread, vector LDG, scalar STS
__device__ __forceinline__ void load_tile(float* sIn, const float* __restrict__ xp,
                                          const float* __restrict__ hp,
                                          int ty0, int tx0, int tid)
{
    if (tid < NHALO) {
        int sy = tid / SWID, sx = tid - sy*SWID;
        int gy = ty0 + sy - 1, gx = tx0 + sx - 1;
        float* dst = sIn + tid * CAP;
        if (gy >= 0 && gy < HH && gx >= 0 && gx < WW) {
            const float2* x2 = (const float2*)(xp + (gy*WW + gx)*CIN);
            float2 a = x2[0], b = x2[1], c = x2[2];
            dst[0]=a.x; dst[1]=a.y; dst[2]=b.x; dst[3]=b.y; dst[4]=c.x; dst[5]=c.y;
            const float4* h4 = (const float4*)(hp + (gy*WW + gx)*FF);
            #pragma unroll
            for (int j = 0; j < 8; ++j) {
                float4 v = h4[j];
                dst[6+4*j]=v.x; dst[7+4*j]=v.y; dst[8+4*j]=v.z; dst[9+4*j]=v.w;
            }
            dst[38] = 0.0f; dst[39] = 0.0f;
        } else {
            #pragma unroll
            for (int i = 0; i < CA_P; ++i) dst[i] = 0.0f;
        }
    }
}

// ---- Persistent kernel: weights resident; 12 steps x (A, B) with grid barriers ----
__global__ void __launch_bounds__(NTHREADS, 1)
gru_persist(const float* __restrict__ x, float* __restrict__ out)
{
    extern __shared__ float sm[];
    float* sIn = sm;                  // NHALO*CAP
    float* sWA = sm + SIN_ELEMS;      // 9*CA_P*FA
    float* sWB = sWA + WA_ELEMS;      // 9*CA_P*FB

    const int dir  = blockIdx.z;
    const int b    = blockIdx.y;
    const int tile = blockIdx.x;
    const int ty0  = (tile / TILESX) * TY;
    const int tx0  = (tile % TILESX) * TX;
    const int tid  = threadIdx.x;

    // weights -> smem ONCE
    {
        const float4* srcA = (const float4*)(g_wA + dir*WA_ELEMS);
        float4* dA = (float4*)sWA;
        for (int i = tid; i < WA_ELEMS/4; i += NTHREADS) dA[i] = srcA[i];
        const float4* srcB = (const float4*)(g_wB + dir*WB_ELEMS);
        float4* dB = (float4*)sWB;
        for (int i = tid; i < WB_ELEMS/4; i += NTHREADS) dB[i] = srcB[i];
    }

    const int g   = tid / PAIRS;          // 0..3 (warp-pure, 160 = 5 warps)
    const int pid = tid - g*PAIRS;
    const int py  = pid / TX, px = pid - py*TX;   // rows py and py+8
    const int gx  = tx0 + px;
    const float* ipb = sIn + (py*SWID + px)*CAP;

    const float* xbase = x + (size_t)(b*TT)*HH*WW*CIN;
    float* hglob  = g_h  + (size_t)((dir*NBATCH + b)*HH*WW)*FF;
    float* zglob  = g_z  + (size_t)((dir*NBATCH + b)*HH*WW)*FF;
    float* rhglob = g_rh + (size_t)((dir*NBATCH + b)*HH*WW)*FF;

    for (int s = 0; s < TT; ++s) {
        const int t = dir ? (TT - 1 - s) : s;
        const float* xp = xbase + (size_t)t*HH*WW*CIN;

        // ================= Phase A: gates =================
        load_tile(sIn, xp, hglob, ty0, tx0, tid);
        __syncthreads();
        {
            unsigned long long acc0[8], acc1[8];
            const unsigned long long* bb = (const unsigned long long*)(g_bA + dir*FA + g*16);
            #pragma unroll
            for (int j = 0; j < 8; ++j) { acc0[j] = bb[j]; acc1[j] = bb[j]; }

            const float* wgb = sWA + g*16;
            #pragma unroll 1
            for (int k = 0; k < 9; ++k) {
                const int ky = k / 3, kx = k - ky*3;
                const float* ip0 = ipb + (ky*SWID + kx)*CAP;
                const float* ip1 = ip0 + 8*SWID*CAP;
                const float* wk  = wgb + k*(CA_P*FA);
                float4 a0 = *(const float4*)(ip0);
                float4 a1 = *(const float4*)(ip1);
                #pragma unroll
                for (int c4 = 0; c4 < CA_P/4; ++c4) {
                    float4 n0, n1;
                    if (c4 < CA_P/4 - 1) {
                        n0 = *(const float4*)(ip0 + 4*(c4+1));
                        n1 = *(const float4*)(ip1 + 4*(c4+1));
                    }
                    const float* wc = wk + 4*c4*FA;
                    #pragma unroll
                    for (int cc = 0; cc < 4; ++cc) {
                        unsigned long long v0 = pack2(((const float*)&a0)[cc]);
                        unsigned long long v1 = pack2(((const float*)&a1)[cc]);
                        const ulonglong2* w2 = (const ulonglong2*)(wc + cc*FA);
                        #pragma unroll
                        for (int j = 0; j < 4; ++j) {
                            ulonglong2 w = w2[j];
                            ffma2(acc0[2*j],   v0, w.x);
                            ffma2(acc0[2*j+1], v0, w.y);
                            ffma2(acc1[2*j],   v1, w.x);
                            ffma2(acc1[2*j+1], v1, w.y);
                        }
                    }
                    a0 = n0; a1 = n1;
                }
            }

            #pragma unroll
            for (int pp = 0; pp < 2; ++pp) {
                const int gy = ty0 + py + 8*pp;
                const unsigned long long* acc = pp ? acc1 : acc0;
                const int base = (gy*WW + gx)*FF;
                if (g < 2) {
                    float4* zp = (float4*)(zglob + base + 16*g);
                    #pragma unroll
                    for (int j = 0; j < 4; ++j) {
                        float a0v,a1v,a2v,a3v;
                        unpack2(acc[2*j],   a0v, a1v);
                        unpack2(acc[2*j+1], a2v, a3v);
                        zp[j] = make_float4(sigm(a0v), sigm(a1v), sigm(a2v), sigm(a3v));
                    }
                } else {
                    const int rf = 16*(g - 2);
                    const float* hin = sIn + ((py + 8*pp + 1)*SWID + (px + 1))*CAP + CIN + rf;
                    float4* rp = (float4*)(rhglob + base + rf);
                    #pragma unroll
                    for (int j = 0; j < 4; ++j) {
                        float a0v,a1v,a2v,a3v;
                        unpack2(acc[2*j],   a0v, a1v);
                        unpack2(acc[2*j+1], a2v, a3v);
                        rp[j] = make_float4(sigm(a0v)*hin[4*j],   sigm(a1v)*hin[4*j+1],
                                            sigm(a2v)*hin[4*j+2], sigm(a3v)*hin[4*j+3]);
                    }
                }
            }
        }
        gridbar(2*s);

        // ================= Phase B: candidate + update =================
        load_tile(sIn, xp, rhglob, ty0, tx0, tid);
        __syncthreads();
        {
            unsigned long long acc0[4], acc1[4];
            const unsigned long long* bb = (const unsigned long long*)(g_bB + dir*FB + g*8);
            #pragma unroll
            for (int j = 0; j < 4; ++j) { acc0[j] = bb[j]; acc1[j] = bb[j]; }

            const float* wgb = sWB + g*8;
            #pragma unroll 1
            for (int k = 0; k < 9; ++k) {
                const int ky = k / 3, kx = k - ky*3;
                const float* ip0 = ipb + (ky*SWID + kx)*CAP;
                const float* ip1 = ip0 + 8*SWID*CAP;
                const float* wk  = wgb + k*(CA_P*FB);
                float4 a0 = *(const float4*)(ip0);
                float4 a1 = *(const float4*)(ip1);
                #pragma unroll
                for (int c4 = 0; c4 < CA_P/4; ++c4) {
                    float4 n0, n1;
                    if (c4 < CA_P/4 - 1) {
                        n0 = *(const float4*)(ip0 + 4*(c4+1));
                        n1 = *(const float4*)(ip1 + 4*(c4+1));
                    }
                    const float* wc = wk + 4*c4*FB;
                    #pragma unroll
                    for (int cc = 0; cc < 4; ++cc) {
                        unsigned long long v0 = pack2(((const float*)&a0)[cc]);
                        unsigned long long v1 = pack2(((const float*)&a1)[cc]);
                        const ulonglong2* w2 = (const ulonglong2*)(wc + cc*FB);
                        #pragma unroll
                        for (int j = 0; j < 2; ++j) {
                            ulonglong2 w = w2[j];
                            ffma2(acc0[2*j],   v0, w.x);
                            ffma2(acc0[2*j+1], v0, w.y);
                            ffma2(acc1[2*j],   v1, w.x);
                            ffma2(acc1[2*j+1], v1, w.y);
                        }
                    }
                    a0 = n0; a1 = n1;
                }
            }

            #pragma unroll
            for (int pp = 0; pp < 2; ++pp) {
                const int gy = ty0 + py + 8*pp;
                const unsigned long long* acc = pp ? acc1 : acc0;
                const int base  = (gy*WW + gx)*FF + 8*g;
                const int obase = (((b*TT + t)*HH + gy)*WW + gx)*(2*FF) + dir*FF + 8*g;
                const float4* zp = (const float4*)(zglob + base);
                const float4* hp = (const float4*)(hglob + base);
                float4* hw = (float4*)(hglob + base);
                float4* ow = (float4*)(out + obase);
                #pragma unroll
                for (int j = 0; j < 2; ++j) {
                    float p0,p1,p2,p3;
                    unpack2(acc[2*j],   p0, p1);
                    unpack2(acc[2*j+1], p2, p3);
                    float4 z = zp[j];
                    float4 h = hp[j];
                    float4 hn;
                    hn.x = z.x*h.x + (1.0f - z.x)*ftanh(p0);
                    hn.y = z.y*h.y + (1.0f - z.y)*ftanh(p1);
                    hn.z = z.z*h.z + (1.0f - z.z)*ftanh(p2);
                    hn.w = z.w*h.w + (1.0f - z.w)*ftanh(p3);
                    hw[j] = hn;
                    ow[j] = hn;
                }
            }
        }
        if (s < TT - 1) gridbar(2*s + 1);
    }
}

extern "C" void kernel_launch(void* const* d_in, const int* in_sizes, int n_in,
                              void* d_out, int out_size)
{
    const float* x    = (const float*)d_in[0];
    const float* WxF  = (const float*)d_in[1];
    const float* bF   = (const float*)d_in[2];
    const float* WzrF = (const float*)d_in[3];
    const float* WhF  = (const float*)d_in[4];
    const float* WxB  = (const float*)d_in[5];
    const float* bB   = (const float*)d_in[6];
    const float* WzrB = (const float*)d_in[7];
    const float* WhB  = (const float*)d_in[8];
    float* out = (float*)d_out;

    const int smemP = (SIN_ELEMS + WA_ELEMS + WB_ELEMS) * 4;   // 207,936 B
    cudaFuncSetAttribute(gru_persist, cudaFuncAttributeMaxDynamicSharedMemorySize, smemP);

    pack_kernel<<<64, 256>>>(WxF, bF, WzrF, WhF, WxB, bB, WzrB, WhB);
    zero_h_kernel<<<256, 256>>>();

    dim3 grid(TILESY * TILESX, NBATCH, 2);   // 30 x 2 x 2 = 120 blocks, all resident
    gru_persist<<<grid, NTHREADS, smemP>>>(x, out);
}

// round 8
// speedup vs baseline: 3.4739x; 3.4739x over previous
#include <cuda_runtime.h>
#include <cuda_fp16.h>
#include <cstdint>

// ---------------- problem constants ----------------
#define HH 80
#define WW 120
#define TT 12
#define FF 32

#define TILY 16
#define TILX 8
#define NTILES 75        // (80/16) * (120/8)
#define NTHREADS 256     // 8 warps; warp = 16-row m-strip

#define HROWS 18
#define HCOLS 10
#define NHALO 180        // 18*10 halo pixels
#define PXF16 48         // real f16 per halo pixel (38 data + 10 zero pad)
#define PXB 112          // padded pixel stride bytes (conflict-free ldmatrix)

#define KW 440           // f16 per weight row (432 = 9 taps * 48, + 8 pad)
#define WRB 880          // weight row stride bytes

#define SM_HALO_B (NHALO*PXB)     // 20160
#define SM_WA_B   (64*WRB)        // 56320
#define SM_WB_B   (32*WRB)        // 28160

// ---------------- global scratch (no allocation allowed) ----------------
__device__ __half g_wAh[2*64*KW];    // packed gate weights   [dir][n=64][k=440]
__device__ __half g_wBh[2*32*KW];    // packed cand. weights  [dir][n=32][k=440]
__device__ float g_h [2*2*HH*WW*FF];
__device__ float g_z [2*2*HH*WW*FF];
__device__ float g_rh[2*2*HH*WW*FF];

// ---------------- helpers ----------------
__device__ __forceinline__ uint32_t smem_u32(const void* p) {
    uint32_t a;
    asm("{ .reg .u64 t; cvta.to.shared.u64 t, %1; cvt.u32.u64 %0, t; }" : "=r"(a) : "l"(p));
    return a;
}
__device__ __forceinline__ float sigm(float v) {
    return __fdividef(1.0f, 1.0f + __expf(-v));
}
__device__ __forceinline__ float ftanh(float v) {
    float e = __expf(-2.0f * v);
    return __fdividef(1.0f - e, 1.0f + e);
}
__device__ __forceinline__ uint32_t h2pack(float a, float b) {
    __half2 h = __floats2half2_rn(a, b);
    return *(uint32_t*)&h;
}
__device__ __forceinline__ void ldm_x4(uint32_t& r0, uint32_t& r1, uint32_t& r2, uint32_t& r3,
                                       uint32_t addr) {
    asm volatile("ldmatrix.sync.aligned.m8n8.x4.shared.b16 {%0,%1,%2,%3}, [%4];"
                 : "=r"(r0), "=r"(r1), "=r"(r2), "=r"(r3) : "r"(addr));
}
__device__ __forceinline__ void mma16816(float* c,
                                         uint32_t a0, uint32_t a1, uint32_t a2, uint32_t a3,
                                         uint32_t b0, uint32_t b1) {
    asm volatile("mma.sync.aligned.m16n8k16.row.col.f32.f16.f16.f32 "
                 "{%0,%1,%2,%3}, {%4,%5,%6,%7}, {%8,%9}, {%0,%1,%2,%3};"
                 : "+f"(c[0]), "+f"(c[1]), "+f"(c[2]), "+f"(c[3])
                 : "r"(a0), "r"(a1), "r"(a2), "r"(a3), "r"(b0), "r"(b1));
}

// ---------------- one-time weight pack to f16 [n][k = tap*48 + c] ----------------
__global__ void pack_kernel(const float* __restrict__ WxF, const float* __restrict__ WzrF,
                            const float* __restrict__ WhF,
                            const float* __restrict__ WxB, const float* __restrict__ WzrB,
                            const float* __restrict__ WhB)
{
    const int TOT = 2*96*KW;
    for (int i = blockIdx.x*blockDim.x + threadIdx.x; i < TOT; i += gridDim.x*blockDim.x) {
        int dir = i / (96*KW); int r = i - dir*(96*KW);
        int n96 = r / KW;      int k = r - n96*KW;
        float v = 0.0f;
        if (k < 432) {
            int tap = k / 48, c = k - tap*48;
            if (c < 38) {
                const float* Wx  = dir ? WxB  : WxF;
                const float* Wzr = dir ? WzrB : WzrF;
                const float* Wh  = dir ? WhB  : WhF;
                if (c < 6)          v = Wx [(tap*6 + c)*96 + n96];
                else if (n96 < 64)  v = Wzr[(tap*32 + (c-6))*64 + n96];
                else                v = Wh [(tap*32 + (c-6))*32 + (n96 - 64)];
            }
        }
        __half hv = __float2half_rn(v);
        if (n96 < 64) g_wAh[(dir*64 + n96)*KW + k]        = hv;
        else          g_wBh[(dir*32 + (n96 - 64))*KW + k] = hv;
    }
}

__global__ void zero_h_kernel() {
    const int n = 2*2*HH*WW*FF;
    for (int i = blockIdx.x*blockDim.x + threadIdx.x; i < n; i += gridDim.x*blockDim.x)
        g_h[i] = 0.0f;
}

// ---------------- halo staging: [x(6) | state(32) | zeros(10)] f16 per pixel ---------
__device__ __forceinline__ void stage_halo(char* sHalo, const float* __restrict__ xp,
                                           const float* __restrict__ hp,
                                           int ty0, int tx0, int tid)
{
    if (tid < NHALO) {
        int sy = tid / HCOLS, sx = tid - sy*HCOLS;
        int gy = ty0 + sy - 1, gx = tx0 + sx - 1;
        uint4* dst = (uint4*)(sHalo + tid*PXB);
        if (gy >= 0 && gy < HH && gx >= 0 && gx < WW) {
            uint32_t u[24];
            const float2* x2 = (const float2*)(xp + (size_t)(gy*WW + gx)*6);
            float2 a0 = x2[0], a1 = x2[1], a2 = x2[2];
            u[0] = h2pack(a0.x, a0.y); u[1] = h2pack(a1.x, a1.y); u[2] = h2pack(a2.x, a2.y);
            const float4* h4 = (const float4*)(hp + (size_t)(gy*WW + gx)*FF);
            #pragma unroll
            for (int j = 0; j < 8; ++j) {
                float4 v = h4[j];
                u[3 + 2*j] = h2pack(v.x, v.y);
                u[4 + 2*j] = h2pack(v.z, v.w);
            }
            u[19] = u[20] = u[21] = u[22] = u[23] = 0u;
            #pragma unroll
            for (int j = 0; j < 6; ++j)
                dst[j] = make_uint4(u[4*j], u[4*j+1], u[4*j+2], u[4*j+3]);
        } else {
            uint4 z = make_uint4(0u, 0u, 0u, 0u);
            #pragma unroll
            for (int j = 0; j < 6; ++j) dst[j] = z;
        }
    }
}

// ---------------- Kernel A: gates via mma.sync -> z, r*h ----------------
__global__ void __launch_bounds__(NTHREADS)
stepA(const float* __restrict__ x, const float* __restrict__ bF,
      const float* __restrict__ bB, int s)
{
    extern __shared__ char smc[];
    char* sHalo = smc;
    char* sW    = smc + SM_HALO_B;

    const int dir = blockIdx.z, b = blockIdx.y, tile = blockIdx.x;
    const int ty0 = (tile / 15) * TILY, tx0 = (tile % 15) * TILX;
    const int t   = dir ? (TT - 1 - s) : s;
    const int tid = threadIdx.x;
    const float* bias = dir ? bB : bF;

    {   // weights -> smem (contiguous copy, pre-packed layout)
        const uint4* src = (const uint4*)(g_wAh + (size_t)dir*64*KW);
        uint4* dst = (uint4*)sW;
        for (int i = tid; i < SM_WA_B/16; i += NTHREADS) dst[i] = src[i];
    }
    const size_t sob = (size_t)(dir*2 + b)*HH*WW*FF;
    stage_halo(sHalo, x + (size_t)(b*TT + t)*HH*WW*6, g_h + sob, ty0, tx0, tid);
    __syncthreads();

    const int warp = tid >> 5, lane = tid & 31;
    const uint32_t haloB = smem_u32(sHalo);
    const uint32_t wB0   = smem_u32(sW);

    // A-fragment addressing: row = m-local = lane&15 -> pixel (py, px)
    const int py  = 2*warp + ((lane & 15) >> 3);
    const int pxl = lane & 7;
    const uint32_t aHalf = (uint32_t)((lane >> 4) << 4);
    // B-fragment addressing (n-pair x4)
    const uint32_t bThr = wB0 + (((uint32_t)((lane >> 4) << 3) + (uint32_t)(lane & 7))*WRB)
                              + (uint32_t)(((lane >> 3) & 1) << 4);

    float C[8][4];
    #pragma unroll
    for (int j = 0; j < 8; ++j) { C[j][0]=C[j][1]=C[j][2]=C[j][3]=0.0f; }

    #pragma unroll
    for (int ky = 0; ky < 3; ++ky)
    #pragma unroll
    for (int kx = 0; kx < 3; ++kx) {
        const int tap = ky*3 + kx;
        const uint32_t aAddr = haloB + (uint32_t)(((py + ky)*HCOLS + pxl + kx)*PXB) + aHalf;
        const uint32_t bTap  = bThr + (uint32_t)(tap*96);
        #pragma unroll
        for (int ch = 0; ch < 3; ++ch) {
            uint32_t a0,a1,a2,a3;
            ldm_x4(a0,a1,a2,a3, aAddr + ch*32);
            #pragma unroll
            for (int jp = 0; jp < 4; ++jp) {
                uint32_t b0,b1,b2,b3;
                ldm_x4(b0,b1,b2,b3, bTap + (uint32_t)(jp*16*WRB) + ch*32);
                mma16816(C[2*jp],     a0,a1,a2,a3, b0,b1);
                mma16816(C[2*jp + 1], a0,a1,a2,a3, b2,b3);
            }
        }
    }

    // epilogue: z = sigm(.), rh = sigm(.)*h
    const int gy0 = ty0 + 2*warp;
    const int gx  = tx0 + (lane >> 2);
    const int fc  = (lane & 3) * 2;
    #pragma unroll
    for (int j = 0; j < 8; ++j) {
        const int f = j*8 + fc;               // n index 0..63 (z:0-31, r:32-63)
        const float b0v = bias[f], b1v = bias[f+1];
        #pragma unroll
        for (int rr = 0; rr < 2; ++rr) {
            const int gy = gy0 + rr;
            const size_t pb = sob + (size_t)(gy*WW + gx)*FF;
            const float v0 = C[j][2*rr]   + b0v;
            const float v1 = C[j][2*rr+1] + b1v;
            if (j < 4) {
                *(float2*)(g_z + pb + f) = make_float2(sigm(v0), sigm(v1));
            } else {
                float2 hv = *(const float2*)(g_h + pb + (f - 32));
                *(float2*)(g_rh + pb + (f - 32)) =
                    make_float2(sigm(v0)*hv.x, sigm(v1)*hv.y);
            }
        }
    }
}

// ---------------- Kernel B: candidate + GRU update ----------------
__global__ void __launch_bounds__(NTHREADS)
stepB(const float* __restrict__ x, const float* __restrict__ bF,
      const float* __restrict__ bB, float* __restrict__ out, int s)
{
    extern __shared__ char smc[];
    char* sHalo = smc;
    char* sW    = smc + SM_HALO_B;

    const int dir = blockIdx.z, b = blockIdx.y, tile = blockIdx.x;
    const int ty0 = (tile / 15) * TILY, tx0 = (tile % 15) * TILX;
    const int t   = dir ? (TT - 1 - s) : s;
    const int tid = threadIdx.x;
    const float* bias = dir ? bB : bF;

    {
        const uint4* src = (const uint4*)(g_wBh + (size_t)dir*32*KW);
        uint4* dst = (uint4*)sW;
        for (int i = tid; i < SM_WB_B/16; i += NTHREADS) dst[i] = src[i];
    }
    const size_t sob = (size_t)(dir*2 + b)*HH*WW*FF;
    stage_halo(sHalo, x + (size_t)(b*TT + t)*HH*WW*6, g_rh + sob, ty0, tx0, tid);
    __syncthreads();

    const int warp = tid >> 5, lane = tid & 31;
    const uint32_t haloB = smem_u32(sHalo);
    const uint32_t wB0   = smem_u32(sW);

    const int py  = 2*warp + ((lane & 15) >> 3);
    const int pxl = lane & 7;
    const uint32_t aHalf = (uint32_t)((lane >> 4) << 4);
    const uint32_t bThr = wB0 + (((uint32_t)((lane >> 4) << 3) + (uint32_t)(lane & 7))*WRB)
                              + (uint32_t)(((lane >> 3) & 1) << 4);

    float C[4][4];
    #pragma unroll
    for (int j = 0; j < 4; ++j) { C[j][0]=C[j][1]=C[j][2]=C[j][3]=0.0f; }

    #pragma unroll
    for (int ky = 0; ky < 3; ++ky)
    #pragma unroll
    for (int kx = 0; kx < 3; ++kx) {
        const int tap = ky*3 + kx;
        const uint32_t aAddr = haloB + (uint32_t)(((py + ky)*HCOLS + pxl + kx)*PXB) + aHalf;
        const uint32_t bTap  = bThr + (uint32_t)(tap*96);
        #pragma unroll
        for (int ch = 0; ch < 3; ++ch) {
            uint32_t a0,a1,a2,a3;
            ldm_x4(a0,a1,a2,a3, aAddr + ch*32);
            #pragma unroll
            for (int jp = 0; jp < 2; ++jp) {
                uint32_t b0,b1,b2,b3;
                ldm_x4(b0,b1,b2,b3, bTap + (uint32_t)(jp*16*WRB) + ch*32);
                mma16816(C[2*jp],     a0,a1,a2,a3, b0,b1);
                mma16816(C[2*jp + 1], a0,a1,a2,a3, b2,b3);
            }
        }
    }

    const int gy0 = ty0 + 2*warp;
    const int gx  = tx0 + (lane >> 2);
    const int fc  = (lane & 3) * 2;
    #pragma unroll
    for (int j = 0; j < 4; ++j) {
        const int f = j*8 + fc;               // 0..31
        const float b0v = bias[64 + f], b1v = bias[64 + f + 1];
        #pragma unroll
        for (int rr = 0; rr < 2; ++rr) {
            const int gy = gy0 + rr;
            const size_t pb = sob + (size_t)(gy*WW + gx)*FF;
            float2 z = *(const float2*)(g_z + pb + f);
            float2 h = *(const float2*)(g_h + pb + f);
            const float hh0 = ftanh(C[j][2*rr]   + b0v);
            const float hh1 = ftanh(C[j][2*rr+1] + b1v);
            float2 hn = make_float2(z.x*h.x + (1.0f - z.x)*hh0,
                                    z.y*h.y + (1.0f - z.y)*hh1);
            *(float2*)(g_h + pb + f) = hn;
            *(float2*)(out + ((size_t)((b*TT + t)*HH + gy)*WW + gx)*64 + dir*32 + f) = hn;
        }
    }
}

extern "C" void kernel_launch(void* const* d_in, const int* in_sizes, int n_in,
                              void* d_out, int out_size)
{
    const float* x    = (const float*)d_in[0];
    const float* WxF  = (const float*)d_in[1];
    const float* bF   = (const float*)d_in[2];
    const float* WzrF = (const float*)d_in[3];
    const float* WhF  = (const float*)d_in[4];
    const float* WxB  = (const float*)d_in[5];
    const float* bB   = (const float*)d_in[6];
    const float* WzrB = (const float*)d_in[7];
    const float* WhB  = (const float*)d_in[8];
    float* out = (float*)d_out;

    const int smA = SM_HALO_B + SM_WA_B;   // 76480 B -> 2 blocks/SM
    const int smB = SM_HALO_B + SM_WB_B;   // 48320 B
    cudaFuncSetAttribute(stepA, cudaFuncAttributeMaxDynamicSharedMemorySize, smA);
    cudaFuncSetAttribute(stepB, cudaFuncAttributeMaxDynamicSharedMemorySize, smB);

    pack_kernel<<<96, 256>>>(WxF, WzrF, WhF, WxB, WzrB, WhB);
    zero_h_kernel<<<256, 256>>>();

    dim3 grid(NTILES, 2, 2);   // 75 tiles x 2 batch x 2 dir = 300 blocks
    for (int s = 0; s < TT; ++s) {
        stepA<<<grid, NTHREADS, smA>>>(x, bF, bB, s);
        stepB<<<grid, NTHREADS, smB>>>(x, bF, bB, out, s);
    }
}